// round 14
// baseline (speedup 1.0000x reference)
#include <cuda_runtime.h>
#include <cuda_bf16.h>
#include <cuda_fp16.h>
#include <cstdint>
#include <math.h>

#define HID   2048
#define HID3  6144
#define NH    16
#define HD    128
#define BATCH 4
#define SEQ   2048
#define MROWS 8192
#define KH    2048          // fp16 operand storage
#define BKG   64            // k-chunk per stage (128B rows)
#define NCHG  32            // pure fp16: 32 chunks
#define GSTAGES 3
#define STG_BYTES 32768     // 16KB A + 16KB B per stage
#define GEMM_SMEM (GSTAGES*STG_BYTES)   // 98304

// attention smem: Q 32KB + 2 stages x (K 16KB + V 16KB) -> 2 CTA/SM
#define KV_STG 32768
#define ATTN_SMEM (32768 + 2*KV_STG)    // 98304

// ---------------- scratch (no allocations allowed) ----------------
__device__ __half g_xc[(size_t)MROWS * KH];
__device__ __half g_wqkvc[(size_t)HID3 * KH];
__device__ __half g_wdc[(size_t)HID * KH];
__device__ __half g_attnc[(size_t)MROWS * KH];
// attention operands (fp16 hi-only): Q,K [bh][s][128] ; V^T [bh][128][s]
__device__ __half g_qs[(size_t)BATCH * NH * SEQ * 128];
__device__ __half g_ks[(size_t)BATCH * NH * SEQ * 128];
__device__ __half g_vt[(size_t)BATCH * NH * 128 * SEQ];

// ---------------- helpers ----------------
__device__ __forceinline__ uint32_t s2u(const void* p) {
    uint32_t a;
    asm("{ .reg .u64 t; cvta.to.shared.u64 t, %1; cvt.u32.u64 %0, t; }"
        : "=r"(a) : "l"(p));
    return a;
}
__device__ __forceinline__ void cp16(uint32_t dst, const void* src) {
    asm volatile("cp.async.cg.shared.global [%0], [%1], 16;"
                 :: "r"(dst), "l"(src));
}
__device__ __forceinline__ void ldsm4(uint32_t* r, uint32_t addr) {
    asm volatile("ldmatrix.sync.aligned.m8n8.x4.shared.b16 {%0,%1,%2,%3}, [%4];"
        : "=r"(r[0]), "=r"(r[1]), "=r"(r[2]), "=r"(r[3]) : "r"(addr));
}
// fp16 mma
__device__ __forceinline__ void mma16816h(float* c, const uint32_t* a,
                                          uint32_t b0, uint32_t b1) {
    asm volatile("mma.sync.aligned.m16n8k16.row.col.f32.f16.f16.f32 "
        "{%0,%1,%2,%3}, {%4,%5,%6,%7}, {%8,%9}, {%0,%1,%2,%3};"
        : "+f"(c[0]), "+f"(c[1]), "+f"(c[2]), "+f"(c[3])
        : "r"(a[0]), "r"(a[1]), "r"(a[2]), "r"(a[3]), "r"(b0), "r"(b1));
}
// pack two fp32 -> fp16x2 (element0 = lo)
__device__ __forceinline__ uint32_t pkhf(float lo, float hi) {
    uint32_t r;
    asm("cvt.rn.f16x2.f32 %0, %1, %2;" : "=r"(r) : "f"(hi), "f"(lo));
    return r;
}

// ---------------- fused convert: all three fp32 -> fp16 tensors (ILP=4) --------
#define N4_X   ((size_t)MROWS * HID / 4)
#define N4_WQ  ((size_t)HID3 * HID / 4)
#define N4_WD  ((size_t)HID * HID / 4)
#define N4_TOT (N4_X + N4_WQ + N4_WD)
__global__ __launch_bounds__(256) void cvt_all_kernel(const float* __restrict__ x,
                                                      const float* __restrict__ wq,
                                                      const float* __restrict__ wd)
{
    size_t base = ((size_t)blockIdx.x * 256 + threadIdx.x) * 4;
#pragma unroll
    for (int u = 0; u < 4; u++) {
        size_t i = base + u;
        if (i >= N4_TOT) return;
        const float* in;
        __half* out;
        size_t rel;
        if (i < N4_X)              { in = x;  out = g_xc;    rel = i; }
        else if (i < N4_X + N4_WQ) { in = wq; out = g_wqkvc; rel = i - N4_X; }
        else                       { in = wd; out = g_wdc;   rel = i - N4_X - N4_WQ; }
        float4 v = ((const float4*)in)[rel];
        ushort4 o = make_ushort4(__half_as_ushort(__float2half(v.x)),
                                 __half_as_ushort(__float2half(v.y)),
                                 __half_as_ushort(__float2half(v.z)),
                                 __half_as_ushort(__float2half(v.w)));
        ((ushort4*)out)[rel] = o;
    }
}

// ============= GEMM mainloop (double-buffered register fragments) ==============
#define GEMM_MAINLOOP(A_, B_)                                                      \
    auto issue = [&](int ch) {                                                     \
        uint32_t st = sb + (ch % GSTAGES) * STG_BYTES;                             \
        const __half* Ab = (A_) + (size_t)ch * BKG;                                \
        const __half* Bb = (B_) + (size_t)ch * BKG;                                \
        _Pragma("unroll")                                                          \
        for (int i = 0; i < 4; i++) {                                              \
            int u = i * 256 + tid;                                                 \
            int r = u >> 3, c = u & 7;                                             \
            uint32_t sw = (uint32_t)(r * 128) + (uint32_t)((c * 16) ^ ((r & 7) << 4)); \
            cp16(st + sw,         Ab + (bm + r) * KH + c * 8);                     \
            cp16(st + 16384 + sw, Bb + (bn + r) * KH + c * 8);                     \
        }                                                                          \
        asm volatile("cp.async.commit_group;");                                    \
    };                                                                             \
    issue(0);                                                                      \
    issue(1);                                                                      \
    float acc[2][8][4];                                                            \
    _Pragma("unroll")                                                              \
    for (int mi = 0; mi < 2; mi++)                                                 \
        _Pragma("unroll")                                                          \
        for (int ni = 0; ni < 8; ni++)                                             \
            _Pragma("unroll")                                                      \
            for (int q = 0; q < 4; q++) acc[mi][ni][q] = 0.f;                      \
    const int lm_row = lane & 15;                                                  \
    const int lm_hi  = (lane >> 4) << 4;                                           \
    uint32_t afr[2][2][4], bfr[2][4][4];                                           \
    auto load_frags = [&](uint32_t st, int kk, uint32_t (*af)[4], uint32_t (*bf)[4]) { \
        _Pragma("unroll")                                                          \
        for (int mi = 0; mi < 2; mi++) {                                           \
            int row = wm * 32 + mi * 16 + lm_row;                                  \
            uint32_t byte = (uint32_t)(kk * 32 + lm_hi);                           \
            ldsm4(af[mi], st + row * 128 + (byte ^ ((row & 7) << 4)));             \
        }                                                                          \
        _Pragma("unroll")                                                          \
        for (int g = 0; g < 4; g++) {                                              \
            int row = wn * 64 + g * 16 + lm_row;                                   \
            uint32_t byte = (uint32_t)(kk * 32 + lm_hi);                           \
            ldsm4(bf[g], st + 16384 + row * 128 + (byte ^ ((row & 7) << 4)));      \
        }                                                                          \
    };                                                                             \
    for (int ch = 0; ch < NCHG; ch++) {                                            \
        asm volatile("cp.async.wait_group 1;");                                    \
        __syncthreads();                                                           \
        if (ch + 2 < NCHG) issue(ch + 2);                                          \
        uint32_t st = sb + (ch % GSTAGES) * STG_BYTES;                             \
        load_frags(st, 0, afr[0], bfr[0]);                                         \
        _Pragma("unroll")                                                          \
        for (int kk = 0; kk < 4; kk++) {                                           \
            const int cur = kk & 1;                                                \
            if (kk < 3) load_frags(st, kk + 1, afr[cur ^ 1], bfr[cur ^ 1]);        \
            _Pragma("unroll")                                                      \
            for (int mi = 0; mi < 2; mi++)                                         \
                _Pragma("unroll")                                                  \
                for (int ni = 0; ni < 8; ni++) {                                   \
                    int g = ni >> 1, h = ni & 1;                                   \
                    mma16816h(acc[mi][ni], afr[cur][mi],                           \
                              bfr[cur][g][h], bfr[cur][g][h + 2]);                 \
                }                                                                  \
        }                                                                          \
    }

// ---------------- QKV GEMM with fused operand epilogue (pure fp16) -------------
__global__ __launch_bounds__(256, 2) void gemm_qkv_kernel(
    const __half* __restrict__ A, const __half* __restrict__ B,
    const float* __restrict__ bias)
{
    extern __shared__ char sm[];
    const uint32_t sb = s2u(sm);
    const int tid = threadIdx.x;
    const int wid = tid >> 5, lane = tid & 31;
    const size_t bm = (size_t)blockIdx.y * 128;
    const size_t bn = (size_t)blockIdx.x * 128;
    const int wm = wid & 3, wn = wid >> 2;

    GEMM_MAINLOOP(A, B)

    // ---- fused epilogue (writes fp16 attention operands, all hi-only) ----
    const int r0 = wm * 32 + (lane >> 2);
    const int c0 = wn * 64 + (lane & 3) * 2;
    const int sec = (int)(bn >> 11);            // 0=Q 1=K 2=V
    const int hh  = ((int)bn & 2047) >> 7;
    const int b_  = (int)(bm >> 11);
    const int s_base = (int)bm & 2047;
    const size_t bh = (size_t)b_ * NH + hh;
    const float qscale = 0.08838834764831845f;

    if (sec < 2) {
        __half* dst = (sec == 0) ? g_qs : g_ks;
        const float sc = (sec == 0) ? qscale : 1.f;
#pragma unroll
        for (int mi = 0; mi < 2; mi++)
#pragma unroll
            for (int ni = 0; ni < 8; ni++) {
                int d = c0 + ni * 8;
                float2 bv = *(const float2*)(bias + bn + d);
                unsigned short h0 = __half_as_ushort(__float2half((acc[mi][ni][0] + bv.x) * sc));
                unsigned short h1 = __half_as_ushort(__float2half((acc[mi][ni][1] + bv.y) * sc));
                unsigned short h2 = __half_as_ushort(__float2half((acc[mi][ni][2] + bv.x) * sc));
                unsigned short h3 = __half_as_ushort(__float2half((acc[mi][ni][3] + bv.y) * sc));
                int ra = s_base + r0 + mi * 16;
                __half* pa = dst + (bh * SEQ + ra) * 128 + d;
                *(ushort2*)pa             = make_ushort2(h0,h1);
                *(ushort2*)(pa + 8 * 128) = make_ushort2(h2,h3);
            }
    } else {
        // V: transpose through smem -> g_vt[bh][d][s] (hi only)
        __syncthreads();
        float* smT = (float*)sm;                 // [128 cols][129]
#pragma unroll
        for (int mi = 0; mi < 2; mi++)
#pragma unroll
            for (int ni = 0; ni < 8; ni++) {
                int d = c0 + ni * 8;
                float2 bv = *(const float2*)(bias + bn + d);
                int ra = r0 + mi * 16;
                smT[d * 129 + ra]           = acc[mi][ni][0] + bv.x;
                smT[(d + 1) * 129 + ra]     = acc[mi][ni][1] + bv.y;
                smT[d * 129 + ra + 8]       = acc[mi][ni][2] + bv.x;
                smT[(d + 1) * 129 + ra + 8] = acc[mi][ni][3] + bv.y;
            }
        __syncthreads();
        const int d = tid >> 1;
        const int sOff = (tid & 1) * 64;
        __half* ph = g_vt + (bh * 128 + d) * SEQ + s_base + sOff;
#pragma unroll
        for (int i = 0; i < 16; i++) {
            int s = i * 4;
            ushort4 o = make_ushort4(
                __half_as_ushort(__float2half(smT[d * 129 + sOff + s + 0])),
                __half_as_ushort(__float2half(smT[d * 129 + sOff + s + 1])),
                __half_as_ushort(__float2half(smT[d * 129 + sOff + s + 2])),
                __half_as_ushort(__float2half(smT[d * 129 + sOff + s + 3])));
            *(ushort4*)(ph + s) = o;
        }
    }
}

// ---------------- dense GEMM (pure fp16, fp32 out) ----------------
__global__ __launch_bounds__(256, 2) void gemm_dense_kernel(
    const __half* __restrict__ A, const __half* __restrict__ B,
    const float* __restrict__ bias, float* __restrict__ C, int Ncols)
{
    extern __shared__ char sm[];
    const uint32_t sb = s2u(sm);
    const int tid = threadIdx.x;
    const int wid = tid >> 5, lane = tid & 31;
    const size_t bm = (size_t)blockIdx.y * 128;
    const size_t bn = (size_t)blockIdx.x * 128;
    const int wm = wid & 3, wn = wid >> 2;

    GEMM_MAINLOOP(A, B)

    const int r0 = wm * 32 + (lane >> 2);
    const int c0 = wn * 64 + (lane & 3) * 2;
#pragma unroll
    for (int mi = 0; mi < 2; mi++)
#pragma unroll
        for (int ni = 0; ni < 8; ni++) {
            size_t col = bn + c0 + ni * 8;
            float2 bv = *(const float2*)(bias + col);
            float* p0 = C + (bm + r0 + mi * 16) * (size_t)Ncols + col;
            float* p1 = p0 + 8 * (size_t)Ncols;
            *(float2*)p0 = make_float2(acc[mi][ni][0] + bv.x, acc[mi][ni][1] + bv.y);
            *(float2*)p1 = make_float2(acc[mi][ni][2] + bv.x, acc[mi][ni][3] + bv.y);
        }
}

// ---------------- fp16 HMMA causal flash attention (2-stage KV, 2 CTA/SM) ------
// grid (16, NH, BATCH) qb reversed; 256 threads = 8 warps x m16 rows.
__global__ __launch_bounds__(256, 2) void attn_hmma_kernel()
{
    extern __shared__ char smc[];
    const uint32_t sb = s2u(smc);
    const int tid = threadIdx.x, w = tid >> 5, lane = tid & 31;
    const int qb = 15 - blockIdx.x, h = blockIdx.y, b = blockIdx.z;
    const int bh = b * NH + h;
    const int nkb = (qb + 1) * 2;
    const int lm_row = lane & 15;
    const int lm_hi  = (lane >> 4) << 4;

    // Q tile: 128 rows x 256B
    {
        const __half* Qg = g_qs + ((size_t)bh * SEQ + qb * 128) * 128;
#pragma unroll
        for (int i = 0; i < 8; i++) {
            int u = i * 256 + tid;
            int r = u >> 4, c = u & 15;
            cp16(sb + r * 256 + ((c * 16) ^ ((r & 7) << 4)), Qg + (size_t)r * 128 + c * 8);
        }
    }
    auto issue_kv = [&](int kb) {
        uint32_t kst = sb + 32768 + (kb & 1) * KV_STG;
        // K: 64 rows x 256B
#pragma unroll
        for (int i = 0; i < 4; i++) {
            int u = i * 256 + tid;
            int r = u >> 4, c = u & 15;
            cp16(kst + r * 256 + ((c * 16) ^ ((r & 7) << 4)),
                 g_ks + ((size_t)bh * SEQ + kb * 64 + r) * 128 + c * 8);
        }
        // V^T: 128 rows x 128B
#pragma unroll
        for (int i = 0; i < 4; i++) {
            int u = i * 256 + tid;
            int r = u >> 3, c = u & 7;
            cp16(kst + 16384 + r * 128 + ((c * 16) ^ ((r & 7) << 4)),
                 g_vt + ((size_t)bh * 128 + r) * SEQ + kb * 64 + c * 8);
        }
        asm volatile("cp.async.commit_group;");
    };
    issue_kv(0);
    if (nkb > 1) issue_kv(1);

    float oacc[16][4];
#pragma unroll
    for (int g = 0; g < 16; g++)
#pragma unroll
        for (int e = 0; e < 4; e++) oacc[g][e] = 0.f;
    float m0 = -1e30f, m1 = -1e30f, lp0 = 0.f, lp1 = 0.f;

    const int row0 = qb * 128 + w * 16 + (lane >> 2);
    const int wrow_max = qb * 128 + w * 16 + 15;

    for (int kb = 0; kb < nkb; kb++) {
        if (kb + 1 < nkb) asm volatile("cp.async.wait_group 1;");
        else              asm volatile("cp.async.wait_group 0;");
        __syncthreads();

        const bool active = (kb * 64) <= wrow_max;
        if (active) {
            const uint32_t kst = sb + 32768 + (kb & 1) * KV_STG;
            const uint32_t vst = kst + 16384;

            // ---- S = Q * K^T (1-term fp16) ----
            float sacc[8][4];
#pragma unroll
            for (int j = 0; j < 8; j++)
#pragma unroll
                for (int e = 0; e < 4; e++) sacc[j][e] = 0.f;

#pragma unroll
            for (int kk = 0; kk < 8; kk++) {
                const int qrow = w * 16 + lm_row;
                uint32_t qa = sb + qrow * 256 +
                              ((uint32_t)(kk * 32 + lm_hi) ^ ((qrow & 7) << 4));
                uint32_t ah[4];
                ldsm4(ah, qa);
#pragma unroll
                for (int g = 0; g < 4; g++) {
                    const int krow = g * 16 + lm_row;
                    uint32_t ka = kst + krow * 256 +
                                  ((uint32_t)(kk * 32 + lm_hi) ^ ((krow & 7) << 4));
                    uint32_t bhh[4];
                    ldsm4(bhh, ka);
                    mma16816h(sacc[2*g],   ah, bhh[0], bhh[2]);
                    mma16816h(sacc[2*g+1], ah, bhh[1], bhh[3]);
                }
            }

            // ---- mask + online softmax ----
            float mx0 = -1e30f, mx1 = -1e30f;
#pragma unroll
            for (int j = 0; j < 8; j++) {
                int colb = kb * 64 + j * 8 + (lane & 3) * 2;
                if (colb     > row0)     sacc[j][0] = -1e30f;
                if (colb + 1 > row0)     sacc[j][1] = -1e30f;
                if (colb     > row0 + 8) sacc[j][2] = -1e30f;
                if (colb + 1 > row0 + 8) sacc[j][3] = -1e30f;
                mx0 = fmaxf(mx0, fmaxf(sacc[j][0], sacc[j][1]));
                mx1 = fmaxf(mx1, fmaxf(sacc[j][2], sacc[j][3]));
            }
            mx0 = fmaxf(mx0, __shfl_xor_sync(0xffffffffu, mx0, 1));
            mx0 = fmaxf(mx0, __shfl_xor_sync(0xffffffffu, mx0, 2));
            mx1 = fmaxf(mx1, __shfl_xor_sync(0xffffffffu, mx1, 1));
            mx1 = fmaxf(mx1, __shfl_xor_sync(0xffffffffu, mx1, 2));
            float mn0 = fmaxf(m0, mx0), mn1 = fmaxf(m1, mx1);
            float al0 = __expf(m0 - mn0), al1 = __expf(m1 - mn1);
            m0 = mn0; m1 = mn1;
            float s0 = 0.f, s1 = 0.f;
#pragma unroll
            for (int j = 0; j < 8; j++) {
                sacc[j][0] = __expf(sacc[j][0] - mn0); s0 += sacc[j][0];
                sacc[j][1] = __expf(sacc[j][1] - mn0); s0 += sacc[j][1];
                sacc[j][2] = __expf(sacc[j][2] - mn1); s1 += sacc[j][2];
                sacc[j][3] = __expf(sacc[j][3] - mn1); s1 += sacc[j][3];
            }
            lp0 = lp0 * al0 + s0;
            lp1 = lp1 * al1 + s1;
#pragma unroll
            for (int g = 0; g < 16; g++) {
                oacc[g][0] *= al0; oacc[g][1] *= al0;
                oacc[g][2] *= al1; oacc[g][3] *= al1;
            }

            // ---- O += P * V (1-term fp16) ----
#pragma unroll
            for (int t = 0; t < 4; t++) {
                const int f0 = 2 * t, f1 = 2 * t + 1;
                uint32_t aPh[4];
                aPh[0] = pkhf(sacc[f0][0], sacc[f0][1]);
                aPh[1] = pkhf(sacc[f0][2], sacc[f0][3]);
                aPh[2] = pkhf(sacc[f1][0], sacc[f1][1]);
                aPh[3] = pkhf(sacc[f1][2], sacc[f1][3]);
#pragma unroll
                for (int g = 0; g < 8; g++) {
                    const int vrow = g * 16 + lm_row;
                    uint32_t va = vst + vrow * 128 +
                                  ((uint32_t)(t * 32 + lm_hi) ^ ((vrow & 7) << 4));
                    uint32_t bhh[4];
                    ldsm4(bhh, va);
                    mma16816h(oacc[2*g],   aPh, bhh[0], bhh[2]);
                    mma16816h(oacc[2*g+1], aPh, bhh[1], bhh[3]);
                }
            }
        }
        // all warps done reading stage kb&1 -> safe to refill it
        __syncthreads();
        if (kb + 2 < nkb) issue_kv(kb + 2);
    }

    lp0 += __shfl_xor_sync(0xffffffffu, lp0, 1);
    lp0 += __shfl_xor_sync(0xffffffffu, lp0, 2);
    lp1 += __shfl_xor_sync(0xffffffffu, lp1, 1);
    lp1 += __shfl_xor_sync(0xffffffffu, lp1, 2);
    const float inv0 = 1.f / lp0, inv1 = 1.f / lp1;

    // ---- write O as plain fp16 (g_attnc, dense GEMM input) ----
    const size_t row = (size_t)b * SEQ + qb * 128 + w * 16 + (lane >> 2);
    const int colb = h * 128 + (lane & 3) * 2;
#pragma unroll
    for (int g = 0; g < 16; g++) {
        int col = colb + g * 8;
        unsigned short h0 = __half_as_ushort(__float2half(oacc[g][0] * inv0));
        unsigned short h1 = __half_as_ushort(__float2half(oacc[g][1] * inv0));
        unsigned short h2 = __half_as_ushort(__float2half(oacc[g][2] * inv1));
        unsigned short h3 = __half_as_ushort(__float2half(oacc[g][3] * inv1));
        __half* pa = g_attnc + row * KH + col;
        *(ushort2*)pa            = make_ushort2(h0,h1);
        *(ushort2*)(pa + 8 * KH) = make_ushort2(h2,h3);
    }
}

// ---------------- launch ----------------
extern "C" void kernel_launch(void* const* d_in, const int* in_sizes, int n_in,
                              void* d_out, int out_size)
{
    (void)in_sizes; (void)n_in; (void)out_size;
    const float* x       = (const float*)d_in[0];
    const float* w_qkv   = (const float*)d_in[1];
    const float* b_qkv   = (const float*)d_in[2];
    const float* w_dense = (const float*)d_in[3];
    const float* b_dense = (const float*)d_in[4];
    float* out = (float*)d_out;

    __half *xc, *wqkvc, *wdc, *attnc;
    cudaGetSymbolAddress((void**)&xc, g_xc);
    cudaGetSymbolAddress((void**)&wqkvc, g_wqkvc);
    cudaGetSymbolAddress((void**)&wdc, g_wdc);
    cudaGetSymbolAddress((void**)&attnc, g_attnc);

    cudaFuncSetAttribute(gemm_qkv_kernel,
                         cudaFuncAttributeMaxDynamicSharedMemorySize, GEMM_SMEM);
    cudaFuncSetAttribute(gemm_dense_kernel,
                         cudaFuncAttributeMaxDynamicSharedMemorySize, GEMM_SMEM);
    cudaFuncSetAttribute(attn_hmma_kernel,
                         cudaFuncAttributeMaxDynamicSharedMemorySize, ATTN_SMEM);

    // fused converts (fp32 -> fp16), ILP=4
    {
        size_t total_thr = (N4_TOT + 3) / 4;
        cvt_all_kernel<<<(unsigned)((total_thr + 255) / 256), 256>>>(x, w_qkv, w_dense);
    }

    // 1) QKV GEMM with fused operand-prep epilogue (pure fp16)
    gemm_qkv_kernel<<<dim3(HID3 / 128, MROWS / 128), 256, GEMM_SMEM>>>(
        xc, wqkvc, b_qkv);

    // 2) fp16 HMMA flash attention (2-stage KV, 2 CTA/SM)
    attn_hmma_kernel<<<dim3(16, NH, BATCH), 256, ATTN_SMEM>>>();

    // 3) out = attn @ Wdense^T + b (pure fp16)
    gemm_dense_kernel<<<dim3(HID / 128, MROWS / 128), 256, GEMM_SMEM>>>(
        attnc, wdc, b_dense, out, HID);
}

// round 15
// speedup vs baseline: 1.0668x; 1.0668x over previous
#include <cuda_runtime.h>
#include <cuda_bf16.h>
#include <cuda_fp16.h>
#include <cstdint>
#include <math.h>

#define HID   2048
#define HID3  6144
#define NH    16
#define HD    128
#define BATCH 4
#define SEQ   2048
#define MROWS 8192
#define KH    2048          // fp16 operand storage
#define BKG   64            // k-chunk per stage (128B rows)
#define NCHG  32            // pure fp16: 32 chunks
#define GSTAGES 3
#define STG_BYTES 32768     // 16KB A + 16KB B per stage
#define GEMM_SMEM (GSTAGES*STG_BYTES)   // 98304

// attention smem: Q 32KB + 3 stages x (K 16KB + V 16KB)
#define KV_STG 32768
#define ATTN_SMEM (32768 + 3*KV_STG)    // 131072

// ---------------- scratch (no allocations allowed) ----------------
__device__ __half g_xc[(size_t)MROWS * KH];
__device__ __half g_wqkvc[(size_t)HID3 * KH];
__device__ __half g_wdc[(size_t)HID * KH];
__device__ __half g_attnc[(size_t)MROWS * KH];
// attention operands (fp16 hi-only): Q,K [bh][s][128] ; V^T [bh][128][s]
__device__ __half g_qs[(size_t)BATCH * NH * SEQ * 128];
__device__ __half g_ks[(size_t)BATCH * NH * SEQ * 128];
__device__ __half g_vt[(size_t)BATCH * NH * 128 * SEQ];

// ---------------- helpers ----------------
__device__ __forceinline__ uint32_t s2u(const void* p) {
    uint32_t a;
    asm("{ .reg .u64 t; cvta.to.shared.u64 t, %1; cvt.u32.u64 %0, t; }"
        : "=r"(a) : "l"(p));
    return a;
}
__device__ __forceinline__ void cp16(uint32_t dst, const void* src) {
    asm volatile("cp.async.cg.shared.global [%0], [%1], 16;"
                 :: "r"(dst), "l"(src));
}
__device__ __forceinline__ void ldsm4(uint32_t* r, uint32_t addr) {
    asm volatile("ldmatrix.sync.aligned.m8n8.x4.shared.b16 {%0,%1,%2,%3}, [%4];"
        : "=r"(r[0]), "=r"(r[1]), "=r"(r[2]), "=r"(r[3]) : "r"(addr));
}
// fp16 mma
__device__ __forceinline__ void mma16816h(float* c, const uint32_t* a,
                                          uint32_t b0, uint32_t b1) {
    asm volatile("mma.sync.aligned.m16n8k16.row.col.f32.f16.f16.f32 "
        "{%0,%1,%2,%3}, {%4,%5,%6,%7}, {%8,%9}, {%0,%1,%2,%3};"
        : "+f"(c[0]), "+f"(c[1]), "+f"(c[2]), "+f"(c[3])
        : "r"(a[0]), "r"(a[1]), "r"(a[2]), "r"(a[3]), "r"(b0), "r"(b1));
}
// pack two fp32 -> fp16x2 (element0 = lo)
__device__ __forceinline__ uint32_t pkhf(float lo, float hi) {
    uint32_t r;
    asm("cvt.rn.f16x2.f32 %0, %1, %2;" : "=r"(r) : "f"(hi), "f"(lo));
    return r;
}

// ---------------- fused convert: all three fp32 -> fp16 tensors (ILP=4) --------
#define N4_X   ((size_t)MROWS * HID / 4)
#define N4_WQ  ((size_t)HID3 * HID / 4)
#define N4_WD  ((size_t)HID * HID / 4)
#define N4_TOT (N4_X + N4_WQ + N4_WD)
__global__ __launch_bounds__(256) void cvt_all_kernel(const float* __restrict__ x,
                                                      const float* __restrict__ wq,
                                                      const float* __restrict__ wd)
{
    size_t base = ((size_t)blockIdx.x * 256 + threadIdx.x) * 4;
#pragma unroll
    for (int u = 0; u < 4; u++) {
        size_t i = base + u;
        if (i >= N4_TOT) return;
        const float* in;
        __half* out;
        size_t rel;
        if (i < N4_X)              { in = x;  out = g_xc;    rel = i; }
        else if (i < N4_X + N4_WQ) { in = wq; out = g_wqkvc; rel = i - N4_X; }
        else                       { in = wd; out = g_wdc;   rel = i - N4_X - N4_WQ; }
        float4 v = ((const float4*)in)[rel];
        ushort4 o = make_ushort4(__half_as_ushort(__float2half(v.x)),
                                 __half_as_ushort(__float2half(v.y)),
                                 __half_as_ushort(__float2half(v.z)),
                                 __half_as_ushort(__float2half(v.w)));
        ((ushort4*)out)[rel] = o;
    }
}

// ============= GEMM mainloop (double-buffered register fragments) ==============
#define GEMM_MAINLOOP(A_, B_)                                                      \
    auto issue = [&](int ch) {                                                     \
        uint32_t st = sb + (ch % GSTAGES) * STG_BYTES;                             \
        const __half* Ab = (A_) + (size_t)ch * BKG;                                \
        const __half* Bb = (B_) + (size_t)ch * BKG;                                \
        _Pragma("unroll")                                                          \
        for (int i = 0; i < 4; i++) {                                              \
            int u = i * 256 + tid;                                                 \
            int r = u >> 3, c = u & 7;                                             \
            uint32_t sw = (uint32_t)(r * 128) + (uint32_t)((c * 16) ^ ((r & 7) << 4)); \
            cp16(st + sw,         Ab + (bm + r) * KH + c * 8);                     \
            cp16(st + 16384 + sw, Bb + (bn + r) * KH + c * 8);                     \
        }                                                                          \
        asm volatile("cp.async.commit_group;");                                    \
    };                                                                             \
    issue(0);                                                                      \
    issue(1);                                                                      \
    float acc[2][8][4];                                                            \
    _Pragma("unroll")                                                              \
    for (int mi = 0; mi < 2; mi++)                                                 \
        _Pragma("unroll")                                                          \
        for (int ni = 0; ni < 8; ni++)                                             \
            _Pragma("unroll")                                                      \
            for (int q = 0; q < 4; q++) acc[mi][ni][q] = 0.f;                      \
    const int lm_row = lane & 15;                                                  \
    const int lm_hi  = (lane >> 4) << 4;                                           \
    uint32_t afr[2][2][4], bfr[2][4][4];                                           \
    auto load_frags = [&](uint32_t st, int kk, uint32_t (*af)[4], uint32_t (*bf)[4]) { \
        _Pragma("unroll")                                                          \
        for (int mi = 0; mi < 2; mi++) {                                           \
            int row = wm * 32 + mi * 16 + lm_row;                                  \
            uint32_t byte = (uint32_t)(kk * 32 + lm_hi);                           \
            ldsm4(af[mi], st + row * 128 + (byte ^ ((row & 7) << 4)));             \
        }                                                                          \
        _Pragma("unroll")                                                          \
        for (int g = 0; g < 4; g++) {                                              \
            int row = wn * 64 + g * 16 + lm_row;                                   \
            uint32_t byte = (uint32_t)(kk * 32 + lm_hi);                           \
            ldsm4(bf[g], st + 16384 + row * 128 + (byte ^ ((row & 7) << 4)));      \
        }                                                                          \
    };                                                                             \
    for (int ch = 0; ch < NCHG; ch++) {                                            \
        asm volatile("cp.async.wait_group 1;");                                    \
        __syncthreads();                                                           \
        if (ch + 2 < NCHG) issue(ch + 2);                                          \
        uint32_t st = sb + (ch % GSTAGES) * STG_BYTES;                             \
        load_frags(st, 0, afr[0], bfr[0]);                                         \
        _Pragma("unroll")                                                          \
        for (int kk = 0; kk < 4; kk++) {                                           \
            const int cur = kk & 1;                                                \
            if (kk < 3) load_frags(st, kk + 1, afr[cur ^ 1], bfr[cur ^ 1]);        \
            _Pragma("unroll")                                                      \
            for (int mi = 0; mi < 2; mi++)                                         \
                _Pragma("unroll")                                                  \
                for (int ni = 0; ni < 8; ni++) {                                   \
                    int g = ni >> 1, h = ni & 1;                                   \
                    mma16816h(acc[mi][ni], afr[cur][mi],                           \
                              bfr[cur][g][h], bfr[cur][g][h + 2]);                 \
                }                                                                  \
        }                                                                          \
    }

// ---------------- QKV GEMM with fused operand epilogue (pure fp16) -------------
__global__ __launch_bounds__(256, 2) void gemm_qkv_kernel(
    const __half* __restrict__ A, const __half* __restrict__ B,
    const float* __restrict__ bias)
{
    extern __shared__ char sm[];
    const uint32_t sb = s2u(sm);
    const int tid = threadIdx.x;
    const int wid = tid >> 5, lane = tid & 31;
    const size_t bm = (size_t)blockIdx.y * 128;
    const size_t bn = (size_t)blockIdx.x * 128;
    const int wm = wid & 3, wn = wid >> 2;

    GEMM_MAINLOOP(A, B)

    // ---- fused epilogue (writes fp16 attention operands, all hi-only) ----
    const int r0 = wm * 32 + (lane >> 2);
    const int c0 = wn * 64 + (lane & 3) * 2;
    const int sec = (int)(bn >> 11);            // 0=Q 1=K 2=V
    const int hh  = ((int)bn & 2047) >> 7;
    const int b_  = (int)(bm >> 11);
    const int s_base = (int)bm & 2047;
    const size_t bh = (size_t)b_ * NH + hh;
    const float qscale = 0.08838834764831845f;

    if (sec < 2) {
        __half* dst = (sec == 0) ? g_qs : g_ks;
        const float sc = (sec == 0) ? qscale : 1.f;
#pragma unroll
        for (int mi = 0; mi < 2; mi++)
#pragma unroll
            for (int ni = 0; ni < 8; ni++) {
                int d = c0 + ni * 8;
                float2 bv = *(const float2*)(bias + bn + d);
                unsigned short h0 = __half_as_ushort(__float2half((acc[mi][ni][0] + bv.x) * sc));
                unsigned short h1 = __half_as_ushort(__float2half((acc[mi][ni][1] + bv.y) * sc));
                unsigned short h2 = __half_as_ushort(__float2half((acc[mi][ni][2] + bv.x) * sc));
                unsigned short h3 = __half_as_ushort(__float2half((acc[mi][ni][3] + bv.y) * sc));
                int ra = s_base + r0 + mi * 16;
                __half* pa = dst + (bh * SEQ + ra) * 128 + d;
                *(ushort2*)pa             = make_ushort2(h0,h1);
                *(ushort2*)(pa + 8 * 128) = make_ushort2(h2,h3);
            }
    } else {
        // V: transpose through smem -> g_vt[bh][d][s] (hi only)
        __syncthreads();
        float* smT = (float*)sm;                 // [128 cols][129]
#pragma unroll
        for (int mi = 0; mi < 2; mi++)
#pragma unroll
            for (int ni = 0; ni < 8; ni++) {
                int d = c0 + ni * 8;
                float2 bv = *(const float2*)(bias + bn + d);
                int ra = r0 + mi * 16;
                smT[d * 129 + ra]           = acc[mi][ni][0] + bv.x;
                smT[(d + 1) * 129 + ra]     = acc[mi][ni][1] + bv.y;
                smT[d * 129 + ra + 8]       = acc[mi][ni][2] + bv.x;
                smT[(d + 1) * 129 + ra + 8] = acc[mi][ni][3] + bv.y;
            }
        __syncthreads();
        const int d = tid >> 1;
        const int sOff = (tid & 1) * 64;
        __half* ph = g_vt + (bh * 128 + d) * SEQ + s_base + sOff;
#pragma unroll
        for (int i = 0; i < 16; i++) {
            int s = i * 4;
            ushort4 o = make_ushort4(
                __half_as_ushort(__float2half(smT[d * 129 + sOff + s + 0])),
                __half_as_ushort(__float2half(smT[d * 129 + sOff + s + 1])),
                __half_as_ushort(__float2half(smT[d * 129 + sOff + s + 2])),
                __half_as_ushort(__float2half(smT[d * 129 + sOff + s + 3])));
            *(ushort4*)(ph + s) = o;
        }
    }
}

// ---------------- dense GEMM (pure fp16, fp32 out) ----------------
__global__ __launch_bounds__(256, 2) void gemm_dense_kernel(
    const __half* __restrict__ A, const __half* __restrict__ B,
    const float* __restrict__ bias, float* __restrict__ C, int Ncols)
{
    extern __shared__ char sm[];
    const uint32_t sb = s2u(sm);
    const int tid = threadIdx.x;
    const int wid = tid >> 5, lane = tid & 31;
    const size_t bm = (size_t)blockIdx.y * 128;
    const size_t bn = (size_t)blockIdx.x * 128;
    const int wm = wid & 3, wn = wid >> 2;

    GEMM_MAINLOOP(A, B)

    const int r0 = wm * 32 + (lane >> 2);
    const int c0 = wn * 64 + (lane & 3) * 2;
#pragma unroll
    for (int mi = 0; mi < 2; mi++)
#pragma unroll
        for (int ni = 0; ni < 8; ni++) {
            size_t col = bn + c0 + ni * 8;
            float2 bv = *(const float2*)(bias + col);
            float* p0 = C + (bm + r0 + mi * 16) * (size_t)Ncols + col;
            float* p1 = p0 + 8 * (size_t)Ncols;
            *(float2*)p0 = make_float2(acc[mi][ni][0] + bv.x, acc[mi][ni][1] + bv.y);
            *(float2*)p1 = make_float2(acc[mi][ni][2] + bv.x, acc[mi][ni][3] + bv.y);
        }
}

// ---------------- fp16 HMMA causal flash attention (3-stage KV, R13 config) ----
// grid (NH*BATCH, 16): x = bh (fastest), y = q-block index (heavy qb first).
__global__ __launch_bounds__(256, 1) void attn_hmma_kernel()
{
    extern __shared__ char smc[];
    const uint32_t sb = s2u(smc);
    const int tid = threadIdx.x, w = tid >> 5, lane = tid & 31;
    const int qb = 15 - blockIdx.y;              // heavy q-blocks in first wave band
    const int bh = blockIdx.x;
    const int b  = bh >> 4, h = bh & 15;
    (void)b; (void)h;
    const int nkb = (qb + 1) * 2;
    const int lm_row = lane & 15;
    const int lm_hi  = (lane >> 4) << 4;

    // Q tile: 128 rows x 256B
    {
        const __half* Qg = g_qs + ((size_t)bh * SEQ + qb * 128) * 128;
#pragma unroll
        for (int i = 0; i < 8; i++) {
            int u = i * 256 + tid;
            int r = u >> 4, c = u & 15;
            cp16(sb + r * 256 + ((c * 16) ^ ((r & 7) << 4)), Qg + (size_t)r * 128 + c * 8);
        }
    }
    auto issue_kv = [&](int kb) {
        uint32_t kst = sb + 32768 + (kb % 3) * KV_STG;
        // K: 64 rows x 256B
#pragma unroll
        for (int i = 0; i < 4; i++) {
            int u = i * 256 + tid;
            int r = u >> 4, c = u & 15;
            cp16(kst + r * 256 + ((c * 16) ^ ((r & 7) << 4)),
                 g_ks + ((size_t)bh * SEQ + kb * 64 + r) * 128 + c * 8);
        }
        // V^T: 128 rows x 128B
#pragma unroll
        for (int i = 0; i < 4; i++) {
            int u = i * 256 + tid;
            int r = u >> 3, c = u & 7;
            cp16(kst + 16384 + r * 128 + ((c * 16) ^ ((r & 7) << 4)),
                 g_vt + ((size_t)bh * 128 + r) * SEQ + kb * 64 + c * 8);
        }
        asm volatile("cp.async.commit_group;");
    };
    issue_kv(0);
    if (nkb > 1) issue_kv(1);

    float oacc[16][4];
#pragma unroll
    for (int g = 0; g < 16; g++)
#pragma unroll
        for (int e = 0; e < 4; e++) oacc[g][e] = 0.f;
    float m0 = -1e30f, m1 = -1e30f, lp0 = 0.f, lp1 = 0.f;

    const int row0 = qb * 128 + w * 16 + (lane >> 2);
    const int wrow_max = qb * 128 + w * 16 + 15;

    for (int kb = 0; kb < nkb; kb++) {
        if (kb + 1 < nkb) asm volatile("cp.async.wait_group 1;");
        else              asm volatile("cp.async.wait_group 0;");
        __syncthreads();
        if (kb + 2 < nkb) issue_kv(kb + 2);

        const bool active = (kb * 64) <= wrow_max;
        if (active) {
            const uint32_t kst = sb + 32768 + (kb % 3) * KV_STG;
            const uint32_t vst = kst + 16384;

            // ---- S = Q * K^T (1-term fp16) ----
            float sacc[8][4];
#pragma unroll
            for (int j = 0; j < 8; j++)
#pragma unroll
                for (int e = 0; e < 4; e++) sacc[j][e] = 0.f;

#pragma unroll
            for (int kk = 0; kk < 8; kk++) {
                const int qrow = w * 16 + lm_row;
                uint32_t qa = sb + qrow * 256 +
                              ((uint32_t)(kk * 32 + lm_hi) ^ ((qrow & 7) << 4));
                uint32_t ah[4];
                ldsm4(ah, qa);
#pragma unroll
                for (int g = 0; g < 4; g++) {
                    const int krow = g * 16 + lm_row;
                    uint32_t ka = kst + krow * 256 +
                                  ((uint32_t)(kk * 32 + lm_hi) ^ ((krow & 7) << 4));
                    uint32_t bhh[4];
                    ldsm4(bhh, ka);
                    mma16816h(sacc[2*g],   ah, bhh[0], bhh[2]);
                    mma16816h(sacc[2*g+1], ah, bhh[1], bhh[3]);
                }
            }

            // ---- mask + online softmax ----
            float mx0 = -1e30f, mx1 = -1e30f;
#pragma unroll
            for (int j = 0; j < 8; j++) {
                int colb = kb * 64 + j * 8 + (lane & 3) * 2;
                if (colb     > row0)     sacc[j][0] = -1e30f;
                if (colb + 1 > row0)     sacc[j][1] = -1e30f;
                if (colb     > row0 + 8) sacc[j][2] = -1e30f;
                if (colb + 1 > row0 + 8) sacc[j][3] = -1e30f;
                mx0 = fmaxf(mx0, fmaxf(sacc[j][0], sacc[j][1]));
                mx1 = fmaxf(mx1, fmaxf(sacc[j][2], sacc[j][3]));
            }
            mx0 = fmaxf(mx0, __shfl_xor_sync(0xffffffffu, mx0, 1));
            mx0 = fmaxf(mx0, __shfl_xor_sync(0xffffffffu, mx0, 2));
            mx1 = fmaxf(mx1, __shfl_xor_sync(0xffffffffu, mx1, 1));
            mx1 = fmaxf(mx1, __shfl_xor_sync(0xffffffffu, mx1, 2));
            float mn0 = fmaxf(m0, mx0), mn1 = fmaxf(m1, mx1);
            float al0 = __expf(m0 - mn0), al1 = __expf(m1 - mn1);
            m0 = mn0; m1 = mn1;
            float s0 = 0.f, s1 = 0.f;
#pragma unroll
            for (int j = 0; j < 8; j++) {
                sacc[j][0] = __expf(sacc[j][0] - mn0); s0 += sacc[j][0];
                sacc[j][1] = __expf(sacc[j][1] - mn0); s0 += sacc[j][1];
                sacc[j][2] = __expf(sacc[j][2] - mn1); s1 += sacc[j][2];
                sacc[j][3] = __expf(sacc[j][3] - mn1); s1 += sacc[j][3];
            }
            lp0 = lp0 * al0 + s0;
            lp1 = lp1 * al1 + s1;
#pragma unroll
            for (int g = 0; g < 16; g++) {
                oacc[g][0] *= al0; oacc[g][1] *= al0;
                oacc[g][2] *= al1; oacc[g][3] *= al1;
            }

            // ---- O += P * V (1-term fp16) ----
#pragma unroll
            for (int t = 0; t < 4; t++) {
                const int f0 = 2 * t, f1 = 2 * t + 1;
                uint32_t aPh[4];
                aPh[0] = pkhf(sacc[f0][0], sacc[f0][1]);
                aPh[1] = pkhf(sacc[f0][2], sacc[f0][3]);
                aPh[2] = pkhf(sacc[f1][0], sacc[f1][1]);
                aPh[3] = pkhf(sacc[f1][2], sacc[f1][3]);
#pragma unroll
                for (int g = 0; g < 8; g++) {
                    const int vrow = g * 16 + lm_row;
                    uint32_t va = vst + vrow * 128 +
                                  ((uint32_t)(t * 32 + lm_hi) ^ ((vrow & 7) << 4));
                    uint32_t bhh[4];
                    ldsm4(bhh, va);
                    mma16816h(oacc[2*g],   aPh, bhh[0], bhh[2]);
                    mma16816h(oacc[2*g+1], aPh, bhh[1], bhh[3]);
                }
            }
        }
    }

    lp0 += __shfl_xor_sync(0xffffffffu, lp0, 1);
    lp0 += __shfl_xor_sync(0xffffffffu, lp0, 2);
    lp1 += __shfl_xor_sync(0xffffffffu, lp1, 1);
    lp1 += __shfl_xor_sync(0xffffffffu, lp1, 2);
    const float inv0 = 1.f / lp0, inv1 = 1.f / lp1;

    // ---- write O as plain fp16 (g_attnc, dense GEMM input) ----
    const int b2 = bh >> 4, h2 = bh & 15;
    const size_t row = (size_t)b2 * SEQ + qb * 128 + w * 16 + (lane >> 2);
    const int colb = h2 * 128 + (lane & 3) * 2;
#pragma unroll
    for (int g = 0; g < 16; g++) {
        int col = colb + g * 8;
        unsigned short h0 = __half_as_ushort(__float2half(oacc[g][0] * inv0));
        unsigned short h1 = __half_as_ushort(__float2half(oacc[g][1] * inv0));
        unsigned short h2u = __half_as_ushort(__float2half(oacc[g][2] * inv1));
        unsigned short h3 = __half_as_ushort(__float2half(oacc[g][3] * inv1));
        __half* pa = g_attnc + row * KH + col;
        *(ushort2*)pa            = make_ushort2(h0,h1);
        *(ushort2*)(pa + 8 * KH) = make_ushort2(h2u,h3);
    }
}

// ---------------- launch ----------------
extern "C" void kernel_launch(void* const* d_in, const int* in_sizes, int n_in,
                              void* d_out, int out_size)
{
    (void)in_sizes; (void)n_in; (void)out_size;
    const float* x       = (const float*)d_in[0];
    const float* w_qkv   = (const float*)d_in[1];
    const float* b_qkv   = (const float*)d_in[2];
    const float* w_dense = (const float*)d_in[3];
    const float* b_dense = (const float*)d_in[4];
    float* out = (float*)d_out;

    __half *xc, *wqkvc, *wdc, *attnc;
    cudaGetSymbolAddress((void**)&xc, g_xc);
    cudaGetSymbolAddress((void**)&wqkvc, g_wqkvc);
    cudaGetSymbolAddress((void**)&wdc, g_wdc);
    cudaGetSymbolAddress((void**)&attnc, g_attnc);

    cudaFuncSetAttribute(gemm_qkv_kernel,
                         cudaFuncAttributeMaxDynamicSharedMemorySize, GEMM_SMEM);
    cudaFuncSetAttribute(gemm_dense_kernel,
                         cudaFuncAttributeMaxDynamicSharedMemorySize, GEMM_SMEM);
    cudaFuncSetAttribute(attn_hmma_kernel,
                         cudaFuncAttributeMaxDynamicSharedMemorySize, ATTN_SMEM);

    // fused converts (fp32 -> fp16), ILP=4
    {
        size_t total_thr = (N4_TOT + 3) / 4;
        cvt_all_kernel<<<(unsigned)((total_thr + 255) / 256), 256>>>(x, w_qkv, w_dense);
    }

    // 1) QKV GEMM with fused operand-prep epilogue (pure fp16)
    gemm_qkv_kernel<<<dim3(HID3 / 128, MROWS / 128), 256, GEMM_SMEM>>>(
        xc, wqkvc, b_qkv);

    // 2) fp16 HMMA flash attention (3-stage KV; heavy q-blocks first)
    attn_hmma_kernel<<<dim3(NH * BATCH, 16), 256, ATTN_SMEM>>>();

    // 3) out = attn @ Wdense^T + b (pure fp16)
    gemm_dense_kernel<<<dim3(HID / 128, MROWS / 128), 256, GEMM_SMEM>>>(
        attnc, wdc, b_dense, out, HID);
}